// round 8
// baseline (speedup 1.0000x reference)
#include <cuda_runtime.h>
#include <math.h>
#include <stdint.h>

// Problem constants
#define BB   64
#define TT   512
#define EE   128
#define HH   256
#define HP   128
#define KK   32
#define SOS  2
#define EOS  3

// LSTM recurrence split: KS h-slices of wh in smem, TAILK in registers
#define KS    48
#define TAILK 80
#define LSTM_SMEM ((KS*512 + 256) * 4)

typedef unsigned long long ull;

__device__ __forceinline__ ull fma2(ull a, ull b, ull c) {
    ull d;
    asm("fma.rn.f32x2 %0, %1, %2, %3;" : "=l"(d) : "l"(a), "l"(b), "l"(c));
    return d;
}
__device__ __forceinline__ ull add2(ull a, ull b) {
    ull d;
    asm("add.rn.f32x2 %0, %1, %2;" : "=l"(d) : "l"(a), "l"(b));
    return d;
}
__device__ __forceinline__ float2 unpack2(ull a) {
    float2 r;
    asm("mov.b64 {%0, %1}, %2;" : "=f"(r.x), "=f"(r.y) : "l"(a));
    return r;
}

// ---------------- device scratch ----------------
__device__ float g_G [ (size_t)BB * TT * 1024 ];   // gate preactivations (warp-permuted rows)
__device__ float g_H0[ (size_t)BB * TT * 256 ];
__device__ float g_H1[ (size_t)BB * TT * 256 ];
__device__ float g_E [ (size_t)BB * TT * 32 ];
__device__ float g_whT[ 4 * 128 * 512 ];           // [dl][k][permuted row]
__device__ float g_wi0[ 1024 * 128 ];              // permuted rows
__device__ float g_wi1[ 1024 * 256 ];
__device__ float g_b0 [ 1024 ];
__device__ float g_b1 [ 1024 ];
__device__ int   g_len[ BB ];

// Warp-gate row permutation.
// New row r -> thread t=r>>1 (warp w=t>>5, lane l=t&31), q=r&1.
// lane l: gate g=l>>3, unit pair p=l&7 -> original row = g*128 + 16*w + 2*p + q.
// So each warp owns all 4 gates of units [16w, 16w+16); the 4 gate values of a
// unit live in lanes p, p+8, p+16, p+24 of the SAME warp.
__device__ __forceinline__ int orow(int r)
{
    int t = r >> 1, q = r & 1;
    int w = t >> 5, l = t & 31;
    int g = l >> 3, p = l & 7;
    return g * 128 + 16 * w + 2 * p + q;
}

// ---------------- lengths ----------------
__global__ void len_kernel(const int* __restrict__ x)
{
    int b = blockIdx.x;
    __shared__ int cnt;
    if (threadIdx.x == 0) cnt = 0;
    __syncthreads();
    int local = 0;
    for (int t = threadIdx.x; t < TT; t += blockDim.x)
        local += (x[b * TT + t] > 0) ? 1 : 0;
    atomicAdd(&cnt, local);
    __syncthreads();
    if (threadIdx.x == 0) g_len[b] = cnt;
}

// ---------------- weight packing: warp-gate permutation + transpose ----------------
__global__ void pack_kernel(const float* __restrict__ wi0f, const float* __restrict__ wi0b,
                            const float* __restrict__ b0f,  const float* __restrict__ b0b,
                            const float* __restrict__ wi1f, const float* __restrict__ wi1b,
                            const float* __restrict__ b1f,  const float* __restrict__ b1b,
                            const float* __restrict__ wh0f, const float* __restrict__ wh0b,
                            const float* __restrict__ wh1f, const float* __restrict__ wh1b)
{
    int tid = blockIdx.x * blockDim.x + threadIdx.x;
    int stride = gridDim.x * blockDim.x;
    for (int i = tid; i < 512 * 128; i += stride) {
        int r = i >> 7, c = i & 127;
        int o = orow(r);
        g_wi0[r * 128 + c]             = wi0f[o * 128 + c];
        g_wi0[512 * 128 + r * 128 + c] = wi0b[o * 128 + c];
    }
    for (int i = tid; i < 512 * 256; i += stride) {
        int r = i >> 8, c = i & 255;
        int o = orow(r);
        g_wi1[r * 256 + c]             = wi1f[o * 256 + c];
        g_wi1[512 * 256 + r * 256 + c] = wi1b[o * 256 + c];
    }
    for (int i = tid; i < 512; i += stride) {
        int o = orow(i);
        g_b0[i]       = b0f[o];
        g_b0[512 + i] = b0b[o];
        g_b1[i]       = b1f[o];
        g_b1[512 + i] = b1b[o];
    }
    const float* whs[4] = { wh0f, wh0b, wh1f, wh1b };
    for (int dl = 0; dl < 4; ++dl) {
        const float* w = whs[dl];
        for (int i = tid; i < 512 * 128; i += stride) {
            int r = i >> 7, k = i & 127;
            g_whT[dl * 65536 + k * 512 + r] = w[orow(r) * 128 + k];
        }
    }
}

// ---------------- fp32 GEMM (R1): C[m][n] = sum_k A[m][k]*B[n][k] + bias[n] ----------------
__global__ void gemm_kernel(const float* __restrict__ Ain, const int* __restrict__ gidx,
                            int Kd, int phase)
{
    __shared__ float As[16][68];
    __shared__ float Bs[16][68];

    int m0 = blockIdx.y * 64;
    int n0 = blockIdx.x * 64;

    {
        int b  = m0 >> 9;
        int t0 = m0 & 511;
        if (t0 >= g_len[b]) return;   // uniform across CTA, before any barrier
    }

    const float* A    = phase ? g_H0  : Ain;
    const float* Bw   = phase ? g_wi1 : g_wi0;
    const float* bias = phase ? g_b1  : g_b0;

    int tid = threadIdx.x;
    int lm = tid >> 2;
    int lk = (tid & 3) * 4;

    int arow_idx = m0 + lm;
    const float* arow = A  + (size_t)(gidx ? gidx[arow_idx] : arow_idx) * Kd;
    const float* brow = Bw + (size_t)(n0 + lm) * Kd;

    int tm = tid & 15;
    int tn = tid >> 4;

    float acc[4][4] = {};

    for (int k0 = 0; k0 < Kd; k0 += 16) {
        float4 av = *(const float4*)(arow + k0 + lk);
        float4 bv = *(const float4*)(brow + k0 + lk);
        __syncthreads();
        As[lk + 0][lm] = av.x; As[lk + 1][lm] = av.y;
        As[lk + 2][lm] = av.z; As[lk + 3][lm] = av.w;
        Bs[lk + 0][lm] = bv.x; Bs[lk + 1][lm] = bv.y;
        Bs[lk + 2][lm] = bv.z; Bs[lk + 3][lm] = bv.w;
        __syncthreads();
#pragma unroll
        for (int kk = 0; kk < 16; ++kk) {
            float4 a = *(const float4*)&As[kk][tm * 4];
            float4 b = *(const float4*)&Bs[kk][tn * 4];
            acc[0][0] += a.x * b.x; acc[0][1] += a.x * b.y; acc[0][2] += a.x * b.z; acc[0][3] += a.x * b.w;
            acc[1][0] += a.y * b.x; acc[1][1] += a.y * b.y; acc[1][2] += a.y * b.z; acc[1][3] += a.y * b.w;
            acc[2][0] += a.z * b.x; acc[2][1] += a.z * b.y; acc[2][2] += a.z * b.z; acc[2][3] += a.z * b.w;
            acc[3][0] += a.w * b.x; acc[3][1] += a.w * b.y; acc[3][2] += a.w * b.z; acc[3][3] += a.w * b.w;
        }
    }

    float4 bo = *(const float4*)&bias[n0 + tn * 4];
#pragma unroll
    for (int i = 0; i < 4; ++i) {
        int m = m0 + tm * 4 + i;
        float4 r;
        r.x = acc[i][0] + bo.x; r.y = acc[i][1] + bo.y;
        r.z = acc[i][2] + bo.z; r.w = acc[i][3] + bo.w;
        *(float4*)&g_G[(size_t)m * 1024 + n0 + tn * 4] = r;
    }
}

// ---------------- LSTM recurrence: single barrier per step ----------------
__device__ __forceinline__ float tanh_mufu(float x) {
    float r;
    asm("tanh.approx.f32 %0, %1;" : "=f"(r) : "f"(x));
    return r;
}
__device__ __forceinline__ float sigm(float x) {
    return fmaf(0.5f, tanh_mufu(0.5f * x), 0.5f);
}

__global__ void __launch_bounds__(256, 1) lstm_kernel(int layer)
{
    int b   = blockIdx.x;
    int dir = blockIdx.y;
    const float* whT = g_whT + (size_t)(layer * 2 + dir) * 65536;  // [k][permuted row]

    extern __shared__ float sm[];
    float* pws   = sm;                  // KS/2 * 256 ulonglong2 (pair-interleaved weights)
    float* hpair = sm + KS * 512;       // 128 float2 (h duplicated)

    int tid  = threadIdx.x;
    int lane = tid & 31;
    int base = lane & 7;

    // pair-interleaved smem weights: one LDS.128 yields (w_k, w_{k+1}) for this thread's rows
    for (int k2 = 0; k2 < KS / 2; ++k2) {
        ull w0 = *(const ull*)&whT[(2 * k2)     * 512 + 2 * tid];
        ull w1 = *(const ull*)&whT[(2 * k2 + 1) * 512 + 2 * tid];
        ulonglong2 v; v.x = w0; v.y = w1;
        *(ulonglong2*)&pws[(k2 * 256 + tid) * 4] = v;
    }

    ull tw[TAILK];
#pragma unroll
    for (int j = 0; j < TAILK; ++j)
        tw[j] = *(const ull*)&whT[(KS + j) * 512 + 2 * tid];

    if (tid < 128) *(float2*)&hpair[2 * tid] = make_float2(0.f, 0.f);
    float2 cc = make_float2(0.f, 0.f);   // cell state, lanes 0-7 of each warp (2 units)
    int len = g_len[b];
    float* Hout = layer ? g_H1 : g_H0;
    __syncthreads();

    const ulonglong2* hp = (const ulonglong2*)hpair;

    int t = (dir == 0) ? 0 : (len - 1);
    ull gc = *(const ull*)&g_G[((size_t)(b * TT + t)) * 1024 + dir * 512 + 2 * tid];

    int u0 = 16 * (tid >> 5) + 2 * base;     // unit pair owned by lanes 0-7
    size_t hbase = (size_t)(b * TT) * 256 + dir * 128 + u0;

    for (int s = 0; s < len; ++s) {
        int sn = s + 1;
        int tnx;
        if (dir == 0) tnx = sn;
        else          tnx = len - 1 - sn;
        if (sn >= len) tnx = t;   // dummy (value unused on last iter)
        ull gn = *(const ull*)&g_G[((size_t)(b * TT + tnx)) * 1024 + dir * 512 + 2 * tid];

        ull acc0 = gc, acc1 = 0, acc2 = 0, acc3 = 0;
#pragma unroll
        for (int k2 = 0; k2 < KS / 2; ++k2) {
            ulonglong2 w  = *(const ulonglong2*)&pws[(k2 * 256 + tid) * 4];
            ulonglong2 hv = hp[k2];
            acc0 = fma2(w.x, hv.x, acc0);
            acc1 = fma2(w.y, hv.y, acc1);
        }
#pragma unroll
        for (int j = 0; j < TAILK; j += 2) {
            ulonglong2 hv = hp[(KS + j) >> 1];
            acc2 = fma2(tw[j],     hv.x, acc2);
            acc3 = fma2(tw[j + 1], hv.y, acc3);
        }
        ull zv = add2(add2(acc0, acc1), add2(acc2, acc3));

        // warp-level gate exchange: lane l holds gate (l>>3) for unit pair (l&7)
        ull zfv = __shfl_sync(0xffffffffu, zv, base + 8);
        ull zgv = __shfl_sync(0xffffffffu, zv, base + 16);
        ull zov = __shfl_sync(0xffffffffu, zv, base + 24);

        if (lane < 8) {
            float2 zi = unpack2(zv);
            float2 zf = unpack2(zfv);
            float2 zg = unpack2(zgv);
            float2 zo = unpack2(zov);
            cc.x = sigm(zf.x) * cc.x + sigm(zi.x) * tanh_mufu(zg.x);
            cc.y = sigm(zf.y) * cc.y + sigm(zi.y) * tanh_mufu(zg.y);
            float h0 = sigm(zo.x) * tanh_mufu(cc.x);
            float h1 = sigm(zo.y) * tanh_mufu(cc.y);
            *(float4*)&hpair[2 * u0] = make_float4(h0, h0, h1, h1);
            *(float2*)&Hout[hbase + (size_t)t * 256] = make_float2(h0, h1);
        }
        __syncthreads();
        gc = gn;
        t  = tnx;
    }
}

// ---------------- emissions: e = H1 @ w_out^T + b_out ----------------
__global__ void emis_kernel(const float* __restrict__ w_out, const float* __restrict__ b_out)
{
    __shared__ float ws[32 * 257];
    __shared__ float hs[8][256];
    __shared__ float bs[32];

    int tid = threadIdx.x;
    for (int i = tid; i < 32 * 256; i += 256)
        ws[(i >> 8) * 257 + (i & 255)] = w_out[i];
    if (tid < 32) bs[tid] = b_out[tid];

    int w    = tid >> 5;
    int lane = tid & 31;
    int m    = blockIdx.x * 8 + w;
    for (int d = lane; d < 256; d += 32)
        hs[w][d] = g_H1[(size_t)m * 256 + d];
    __syncthreads();

    float e = bs[lane];
#pragma unroll 8
    for (int d = 0; d < 256; ++d)
        e += hs[w][d] * ws[lane * 257 + d];
    g_E[(size_t)m * 32 + lane] = e;
}

// ---------------- CRF: warp per batch ----------------
__global__ void crf_kernel(const int* __restrict__ y, const float* __restrict__ trans,
                           float* __restrict__ out)
{
    int b    = blockIdx.x;
    int lane = threadIdx.x;
    __shared__ float tr[32 * 33];
    for (int i = lane; i < 1024; i += 32)
        tr[(i >> 5) * 33 + (i & 31)] = trans[i];
    __syncwarp();

    int len = g_len[b];
    const float* Eb = g_E + (size_t)b * TT * 32;

    float score = (lane == SOS) ? 0.f : -10000.f;
    for (int t = 0; t < len; ++t) {
        float e = Eb[t * 32 + lane];
        float v[32];
#pragma unroll
        for (int k = 0; k < 32; ++k)
            v[k] = __shfl_sync(0xffffffffu, score, k) + tr[lane * 33 + k];
        float m = v[0];
#pragma unroll
        for (int k = 1; k < 32; ++k) m = fmaxf(m, v[k]);
        float s = 0.f;
#pragma unroll
        for (int k = 0; k < 32; ++k) s += expf(v[k] - m);
        score = e + m + logf(s);
    }

    float v2 = score + tr[EOS * 33 + lane];
    float m = v2;
#pragma unroll
    for (int off = 16; off; off >>= 1) m = fmaxf(m, __shfl_xor_sync(0xffffffffu, m, off));
    float s = expf(v2 - m);
#pragma unroll
    for (int off = 16; off; off >>= 1) s += __shfl_xor_sync(0xffffffffu, s, off);
    float logZ = m + logf(s);

    const int* yb = y + b * (TT + 1);
    float g = 0.f;
    for (int t = lane; t < len; t += 32) {
        int y1 = yb[t + 1];
        int y0 = yb[t];
        g += Eb[t * 32 + y1] + tr[y1 * 33 + y0];
    }
#pragma unroll
    for (int off = 16; off; off >>= 1) g += __shfl_xor_sync(0xffffffffu, g, off);

    if (lane == 0) {
        g += tr[EOS * 33 + yb[len]];
        out[b] = logZ - g;
    }
}

// ---------------- launch ----------------
extern "C" void kernel_launch(void* const* d_in, const int* in_sizes, int n_in,
                              void* d_out, int out_size)
{
    const int*   x      = (const int*)  d_in[0];
    const int*   y      = (const int*)  d_in[1];
    const float* embed  = (const float*)d_in[2];
    const float* wi_l0f = (const float*)d_in[3];
    const float* wh_l0f = (const float*)d_in[4];
    const float* b_l0f  = (const float*)d_in[5];
    const float* wi_l0b = (const float*)d_in[6];
    const float* wh_l0b = (const float*)d_in[7];
    const float* b_l0b  = (const float*)d_in[8];
    const float* wi_l1f = (const float*)d_in[9];
    const float* wh_l1f = (const float*)d_in[10];
    const float* b_l1f  = (const float*)d_in[11];
    const float* wi_l1b = (const float*)d_in[12];
    const float* wh_l1b = (const float*)d_in[13];
    const float* b_l1b  = (const float*)d_in[14];
    const float* w_out  = (const float*)d_in[15];
    const float* b_out  = (const float*)d_in[16];
    const float* trans  = (const float*)d_in[17];
    float* out = (float*)d_out;

    cudaFuncSetAttribute(lstm_kernel, cudaFuncAttributeMaxDynamicSharedMemorySize, LSTM_SMEM);

    len_kernel<<<BB, 256>>>(x);
    pack_kernel<<<256, 256>>>(wi_l0f, wi_l0b, b_l0f, b_l0b,
                              wi_l1f, wi_l1b, b_l1f, b_l1b,
                              wh_l0f, wh_l0b, wh_l1f, wh_l1b);

    gemm_kernel<<<dim3(16, 512), 256>>>(embed, x, 128, 0);
    lstm_kernel<<<dim3(BB, 2), 256, LSTM_SMEM>>>(0);

    gemm_kernel<<<dim3(16, 512), 256>>>(nullptr, nullptr, 256, 1);
    lstm_kernel<<<dim3(BB, 2), 256, LSTM_SMEM>>>(1);

    emis_kernel<<<(BB * TT) / 8, 256>>>(w_out, b_out);
    crf_kernel<<<BB, 32>>>(y, trans, out);
}

// round 9
// speedup vs baseline: 1.0924x; 1.0924x over previous
#include <cuda_runtime.h>
#include <cuda_bf16.h>
#include <math.h>
#include <stdint.h>

// Problem constants
#define BB   64
#define TT   512
#define EE   128
#define HH   256
#define HP   128
#define KK   32
#define SOS  2
#define EOS  3

// LSTM recurrence split: KS h-slices of wh in smem (bf16), TAILK in registers (fp32)
#define KS    48
#define TAILK 80
#define LSTM_SMEM (KS*512*2 + (512 + 256) * 4)

typedef unsigned long long ull;

__device__ __forceinline__ ull fma2(ull a, ull b, ull c) {
    ull d;
    asm("fma.rn.f32x2 %0, %1, %2, %3;" : "=l"(d) : "l"(a), "l"(b), "l"(c));
    return d;
}
__device__ __forceinline__ ull add2(ull a, ull b) {
    ull d;
    asm("add.rn.f32x2 %0, %1, %2;" : "=l"(d) : "l"(a), "l"(b));
    return d;
}
__device__ __forceinline__ float2 unpack2(ull a) {
    float2 r;
    asm("mov.b64 {%0, %1}, %2;" : "=f"(r.x), "=f"(r.y) : "l"(a));
    return r;
}
// packed (bf16 lo, bf16 hi) -> f32x2 pair (exact: bf16 is top 16 bits of f32)
__device__ __forceinline__ ull bf2up(uint32_t r) {
    ull d;
    asm("{ .reg .b32 lo, hi;\n\t"
        "  shl.b32 lo, %1, 16;\n\t"
        "  and.b32 hi, %1, 0xFFFF0000;\n\t"
        "  mov.b64 %0, {lo, hi}; }"
        : "=l"(d) : "r"(r));
    return d;
}

// ---------------- device scratch ----------------
__device__ float g_G [ (size_t)BB * TT * 1024 ];   // gate preactivations, both dirs
__device__ float g_H0[ (size_t)BB * TT * 256 ];
__device__ float g_H1[ (size_t)BB * TT * 256 ];
__device__ float g_E [ (size_t)BB * TT * 32 ];
__device__ float g_whT[ 4 * 128 * 512 ];           // [dl][k][512]
__device__ float g_wi0[ 1024 * 128 ];
__device__ float g_wi1[ 1024 * 256 ];
__device__ float g_b0 [ 1024 ];
__device__ float g_b1 [ 1024 ];
__device__ int   g_len[ BB ];

// ---------------- lengths ----------------
__global__ void len_kernel(const int* __restrict__ x)
{
    int b = blockIdx.x;
    __shared__ int cnt;
    if (threadIdx.x == 0) cnt = 0;
    __syncthreads();
    int local = 0;
    for (int t = threadIdx.x; t < TT; t += blockDim.x)
        local += (x[b * TT + t] > 0) ? 1 : 0;
    atomicAdd(&cnt, local);
    __syncthreads();
    if (threadIdx.x == 0) g_len[b] = cnt;
}

// ---------------- weight packing / transposition ----------------
__global__ void pack_kernel(const float* __restrict__ wi0f, const float* __restrict__ wi0b,
                            const float* __restrict__ b0f,  const float* __restrict__ b0b,
                            const float* __restrict__ wi1f, const float* __restrict__ wi1b,
                            const float* __restrict__ b1f,  const float* __restrict__ b1b,
                            const float* __restrict__ wh0f, const float* __restrict__ wh0b,
                            const float* __restrict__ wh1f, const float* __restrict__ wh1b)
{
    int tid = blockIdx.x * blockDim.x + threadIdx.x;
    int stride = gridDim.x * blockDim.x;
    for (int i = tid; i < 512 * 128; i += stride) {
        g_wi0[i]             = wi0f[i];
        g_wi0[512 * 128 + i] = wi0b[i];
    }
    for (int i = tid; i < 512 * 256; i += stride) {
        g_wi1[i]             = wi1f[i];
        g_wi1[512 * 256 + i] = wi1b[i];
    }
    for (int i = tid; i < 512; i += stride) {
        g_b0[i]       = b0f[i];
        g_b0[512 + i] = b0b[i];
        g_b1[i]       = b1f[i];
        g_b1[512 + i] = b1b[i];
    }
    const float* whs[4] = { wh0f, wh0b, wh1f, wh1b };
    for (int dl = 0; dl < 4; ++dl) {
        const float* w = whs[dl];
        for (int i = tid; i < 512 * 128; i += stride) {
            int r = i >> 7, k = i & 127;
            g_whT[dl * 65536 + k * 512 + r] = w[i];   // whT[k][r] = wh[r][k]
        }
    }
}

// ---------------- fp32 GEMM (R1): C[m][n] = sum_k A[m][k]*B[n][k] + bias[n] ----------------
// Skips blocks whose entire t-range is padding (output never consumed).
__global__ void gemm_kernel(const float* __restrict__ Ain, const int* __restrict__ gidx,
                            int Kd, int phase)
{
    __shared__ float As[16][68];
    __shared__ float Bs[16][68];

    int m0 = blockIdx.y * 64;
    int n0 = blockIdx.x * 64;

    {
        int b  = m0 >> 9;
        int t0 = m0 & 511;
        if (t0 >= g_len[b]) return;   // uniform across CTA, before any barrier
    }

    const float* A    = phase ? g_H0  : Ain;
    const float* Bw   = phase ? g_wi1 : g_wi0;
    const float* bias = phase ? g_b1  : g_b0;

    int tid = threadIdx.x;
    int lm = tid >> 2;
    int lk = (tid & 3) * 4;

    int arow_idx = m0 + lm;
    const float* arow = A  + (size_t)(gidx ? gidx[arow_idx] : arow_idx) * Kd;
    const float* brow = Bw + (size_t)(n0 + lm) * Kd;

    int tm = tid & 15;
    int tn = tid >> 4;

    float acc[4][4] = {};

    for (int k0 = 0; k0 < Kd; k0 += 16) {
        float4 av = *(const float4*)(arow + k0 + lk);
        float4 bv = *(const float4*)(brow + k0 + lk);
        __syncthreads();
        As[lk + 0][lm] = av.x; As[lk + 1][lm] = av.y;
        As[lk + 2][lm] = av.z; As[lk + 3][lm] = av.w;
        Bs[lk + 0][lm] = bv.x; Bs[lk + 1][lm] = bv.y;
        Bs[lk + 2][lm] = bv.z; Bs[lk + 3][lm] = bv.w;
        __syncthreads();
#pragma unroll
        for (int kk = 0; kk < 16; ++kk) {
            float4 a = *(const float4*)&As[kk][tm * 4];
            float4 b = *(const float4*)&Bs[kk][tn * 4];
            acc[0][0] += a.x * b.x; acc[0][1] += a.x * b.y; acc[0][2] += a.x * b.z; acc[0][3] += a.x * b.w;
            acc[1][0] += a.y * b.x; acc[1][1] += a.y * b.y; acc[1][2] += a.y * b.z; acc[1][3] += a.y * b.w;
            acc[2][0] += a.z * b.x; acc[2][1] += a.z * b.y; acc[2][2] += a.z * b.z; acc[2][3] += a.z * b.w;
            acc[3][0] += a.w * b.x; acc[3][1] += a.w * b.y; acc[3][2] += a.w * b.z; acc[3][3] += a.w * b.w;
        }
    }

    float4 bo = *(const float4*)&bias[n0 + tn * 4];
#pragma unroll
    for (int i = 0; i < 4; ++i) {
        int m = m0 + tm * 4 + i;
        float4 r;
        r.x = acc[i][0] + bo.x; r.y = acc[i][1] + bo.y;
        r.z = acc[i][2] + bo.z; r.w = acc[i][3] + bo.w;
        *(float4*)&g_G[(size_t)m * 1024 + n0 + tn * 4] = r;
    }
}

// ---------------- LSTM recurrence (R7 structure, bf16 smem weights) ----------------
__device__ __forceinline__ float tanh_mufu(float x) {
    float r;
    asm("tanh.approx.f32 %0, %1;" : "=f"(r) : "f"(x));
    return r;
}
__device__ __forceinline__ float sigm(float x) {
    return fmaf(0.5f, tanh_mufu(0.5f * x), 0.5f);
}

__global__ void __launch_bounds__(256, 1) lstm_kernel(int layer)
{
    int b   = blockIdx.x;
    int dir = blockIdx.y;
    const float* whT = g_whT + (size_t)(layer * 2 + dir) * 65536;  // [k][512]

    extern __shared__ float sm[];
    uint32_t* pwsb = (uint32_t*)sm;                    // KS*256 u32: packed bf16 row-pairs
    float* zbuf  = sm + (KS * 512 * 2) / 4;            // 512
    float* hpair = zbuf + 512;                         // 128 float2 (h duplicated)

    int tid = threadIdx.x;

    // pack smem weights to bf16 pairs: chunk c holds k-slices 4c..4c+3 for this thread
    for (int c = 0; c < KS / 4; ++c) {
        uint32_t v[4];
#pragma unroll
        for (int j = 0; j < 4; ++j) {
            float2 w = *(const float2*)&whT[(4 * c + j) * 512 + 2 * tid];
            __nv_bfloat162 bb = __float22bfloat162_rn(w);
            v[j] = *(uint32_t*)&bb;
        }
        *(uint4*)&pwsb[(c * 256 + tid) * 4] = make_uint4(v[0], v[1], v[2], v[3]);
    }

    ull tw[TAILK];
#pragma unroll
    for (int j = 0; j < TAILK; ++j)
        tw[j] = *(const ull*)&whT[(KS + j) * 512 + 2 * tid];

    if (tid < 128) *(float2*)&hpair[2 * tid] = make_float2(0.f, 0.f);
    float c_st = 0.f;
    int len = g_len[b];
    float* Hout = layer ? g_H1 : g_H0;
    __syncthreads();

    const ulonglong2* hp = (const ulonglong2*)hpair;

    int t = (dir == 0) ? 0 : (len - 1);
    ull gc = *(const ull*)&g_G[((size_t)(b * TT + t)) * 1024 + dir * 512 + 2 * tid];

    for (int s = 0; s < len; ++s) {
        int sn = s + 1;
        int tnx;
        if (dir == 0) tnx = sn;
        else          tnx = len - 1 - sn;
        if (sn >= len) tnx = t;   // dummy (value unused on last iter)
        ull gn = *(const ull*)&g_G[((size_t)(b * TT + tnx)) * 1024 + dir * 512 + 2 * tid];

        ull acc0 = gc, acc1 = 0, acc2 = 0, acc3 = 0;
#pragma unroll
        for (int c = 0; c < KS / 4; ++c) {
            uint4 w4 = *(const uint4*)&pwsb[(c * 256 + tid) * 4];
            ulonglong2 hv0 = hp[2 * c];
            ulonglong2 hv1 = hp[2 * c + 1];
            acc0 = fma2(bf2up(w4.x), hv0.x, acc0);
            acc1 = fma2(bf2up(w4.y), hv0.y, acc1);
            acc2 = fma2(bf2up(w4.z), hv1.x, acc2);
            acc3 = fma2(bf2up(w4.w), hv1.y, acc3);
        }
#pragma unroll
        for (int j = 0; j < TAILK; j += 2) {
            ulonglong2 hv = hp[(KS + j) >> 1];
            acc0 = fma2(tw[j],     hv.x, acc0);
            acc1 = fma2(tw[j + 1], hv.y, acc1);
        }
        float2 z = unpack2(add2(add2(acc0, acc1), add2(acc2, acc3)));
        *(float2*)&zbuf[2 * tid] = z;
        __syncthreads();

        if (tid < 128) {
            float zi = zbuf[tid],       zf = zbuf[128 + tid];
            float zg = zbuf[256 + tid], zo = zbuf[384 + tid];
            c_st = sigm(zf) * c_st + sigm(zi) * tanh_mufu(zg);
            float h = sigm(zo) * tanh_mufu(c_st);
            *(float2*)&hpair[2 * tid] = make_float2(h, h);
            Hout[((size_t)(b * TT + t)) * 256 + dir * 128 + tid] = h;
        }
        __syncthreads();
        gc = gn;
        t  = tnx;
    }
}

// ---------------- emissions: e = H1 @ w_out^T + b_out ----------------
__global__ void emis_kernel(const float* __restrict__ w_out, const float* __restrict__ b_out)
{
    __shared__ float ws[32 * 257];
    __shared__ float hs[8][256];
    __shared__ float bs[32];

    int tid = threadIdx.x;
    for (int i = tid; i < 32 * 256; i += 256)
        ws[(i >> 8) * 257 + (i & 255)] = w_out[i];
    if (tid < 32) bs[tid] = b_out[tid];

    int w    = tid >> 5;
    int lane = tid & 31;
    int m    = blockIdx.x * 8 + w;
    for (int d = lane; d < 256; d += 32)
        hs[w][d] = g_H1[(size_t)m * 256 + d];
    __syncthreads();

    float e = bs[lane];
#pragma unroll 8
    for (int d = 0; d < 256; ++d)
        e += hs[w][d] * ws[lane * 257 + d];
    g_E[(size_t)m * 32 + lane] = e;
}

// ---------------- CRF: warp per batch ----------------
__global__ void crf_kernel(const int* __restrict__ y, const float* __restrict__ trans,
                           float* __restrict__ out)
{
    int b    = blockIdx.x;
    int lane = threadIdx.x;
    __shared__ float tr[32 * 33];
    for (int i = lane; i < 1024; i += 32)
        tr[(i >> 5) * 33 + (i & 31)] = trans[i];
    __syncwarp();

    int len = g_len[b];
    const float* Eb = g_E + (size_t)b * TT * 32;

    float score = (lane == SOS) ? 0.f : -10000.f;
    for (int t = 0; t < len; ++t) {
        float e = Eb[t * 32 + lane];
        float v[32];
#pragma unroll
        for (int k = 0; k < 32; ++k)
            v[k] = __shfl_sync(0xffffffffu, score, k) + tr[lane * 33 + k];
        float m = v[0];
#pragma unroll
        for (int k = 1; k < 32; ++k) m = fmaxf(m, v[k]);
        float s = 0.f;
#pragma unroll
        for (int k = 0; k < 32; ++k) s += expf(v[k] - m);
        score = e + m + logf(s);
    }

    float v2 = score + tr[EOS * 33 + lane];
    float m = v2;
#pragma unroll
    for (int off = 16; off; off >>= 1) m = fmaxf(m, __shfl_xor_sync(0xffffffffu, m, off));
    float s = expf(v2 - m);
#pragma unroll
    for (int off = 16; off; off >>= 1) s += __shfl_xor_sync(0xffffffffu, s, off);
    float logZ = m + logf(s);

    const int* yb = y + b * (TT + 1);
    float g = 0.f;
    for (int t = lane; t < len; t += 32) {
        int y1 = yb[t + 1];
        int y0 = yb[t];
        g += Eb[t * 32 + y1] + tr[y1 * 33 + y0];
    }
#pragma unroll
    for (int off = 16; off; off >>= 1) g += __shfl_xor_sync(0xffffffffu, g, off);

    if (lane == 0) {
        g += tr[EOS * 33 + yb[len]];
        out[b] = logZ - g;
    }
}

// ---------------- launch ----------------
extern "C" void kernel_launch(void* const* d_in, const int* in_sizes, int n_in,
                              void* d_out, int out_size)
{
    const int*   x      = (const int*)  d_in[0];
    const int*   y      = (const int*)  d_in[1];
    const float* embed  = (const float*)d_in[2];
    const float* wi_l0f = (const float*)d_in[3];
    const float* wh_l0f = (const float*)d_in[4];
    const float* b_l0f  = (const float*)d_in[5];
    const float* wi_l0b = (const float*)d_in[6];
    const float* wh_l0b = (const float*)d_in[7];
    const float* b_l0b  = (const float*)d_in[8];
    const float* wi_l1f = (const float*)d_in[9];
    const float* wh_l1f = (const float*)d_in[10];
    const float* b_l1f  = (const float*)d_in[11];
    const float* wi_l1b = (const float*)d_in[12];
    const float* wh_l1b = (const float*)d_in[13];
    const float* b_l1b  = (const float*)d_in[14];
    const float* w_out  = (const float*)d_in[15];
    const float* b_out  = (const float*)d_in[16];
    const float* trans  = (const float*)d_in[17];
    float* out = (float*)d_out;

    cudaFuncSetAttribute(lstm_kernel, cudaFuncAttributeMaxDynamicSharedMemorySize, LSTM_SMEM);

    len_kernel<<<BB, 256>>>(x);
    pack_kernel<<<256, 256>>>(wi_l0f, wi_l0b, b_l0f, b_l0b,
                              wi_l1f, wi_l1b, b_l1f, b_l1b,
                              wh_l0f, wh_l0b, wh_l1f, wh_l1b);

    gemm_kernel<<<dim3(16, 512), 256>>>(embed, x, 128, 0);
    lstm_kernel<<<dim3(BB, 2), 256, LSTM_SMEM>>>(0);

    gemm_kernel<<<dim3(16, 512), 256>>>(nullptr, nullptr, 256, 1);
    lstm_kernel<<<dim3(BB, 2), 256, LSTM_SMEM>>>(1);

    emis_kernel<<<(BB * TT) / 8, 256>>>(w_out, b_out);
    crf_kernel<<<BB, 32>>>(y, trans, out);
}